// round 13
// baseline (speedup 1.0000x reference)
#include <cuda_runtime.h>

// DeEmphasis: y[n] = x[n] + ALPHA*y[n-1], zero init, per row (64 x 960000 fp32).
//
// R13: continue the only gradient that has moved the bench (R1 256thr/SEG32
// 79.0 -> R12 512thr/SEG16 78.8): 1024 threads, SEG=8, launch_bounds(1024,2)
// -> 2048 resident threads/SM. Serial FMA chains halve again; 32 warps/block
// drive the staging bursts. Everything else frozen (CHUNK=8000, HALO=192,
// 7680 blocks, padded smem layout, plain cached ld/st).
// Layout: lane t base bank = (8t + t/4) mod 32 is a permutation -> conflict-
// free. Cross-warp carry coef alpha^256 ~ 8.5e-19 -> prev-warp total exact.

#define ALPHA 0.85f

static constexpr int ROWLEN  = 960000;
static constexpr int CHUNK   = 8000;   // payload per block
static constexpr int HALO    = 192;    // alpha^192 ~ 2e-14, below fp32 eps
static constexpr int TOTAL   = CHUNK + HALO;      // 8192
static constexpr int THREADS = 1024;
static constexpr int SEG     = TOTAL / THREADS;   // 8 elems per thread
static constexpr int SPAD    = TOTAL + TOTAL / 32; // 8448 floats, +1 pad / 32

// compile-time alpha^n
__host__ __device__ constexpr float apow(int n) {
    double r = 1.0;
    for (int i = 0; i < n; i++) r *= (double)ALPHA;
    return (float)r;
}

__global__ void __launch_bounds__(THREADS, 2)
deemph_kernel(const float* __restrict__ x, float* __restrict__ y)
{
    const int chunk = blockIdx.x;          // 0..119
    const int row   = blockIdx.y;          // 0..63
    const int tid   = threadIdx.x;
    const int lane  = tid & 31;
    const int w     = tid >> 5;            // 0..31

    __shared__ float s[SPAD];
    __shared__ float wsum[THREADS / 32];

    const int rowbase = row * ROWLEN;
    const int cstart  = chunk * CHUNK - HALO;   // first (halo) column, may be <0

    // ---- stage in: coalesced global -> padded smem ----
    #pragma unroll
    for (int p = 0; p < TOTAL / THREADS; p++) {
        int i   = tid + p * THREADS;
        int col = cstart + i;
        float v = (col >= 0) ? x[rowbase + col] : 0.0f;   // zero-init history
        s[i + (i >> 5)] = v;
    }
    __syncthreads();

    // ---- per-thread segment into registers (padded layout, conflict-free) ----
    float xv[SEG];
    const int sbase = tid * SEG + (tid * SEG >> 5);
    #pragma unroll
    for (int j = 0; j < SEG; j++) xv[j] = s[sbase + j];

    // pass 1: segment total with zero entering state
    float b = 0.0f;
    #pragma unroll
    for (int j = 0; j < SEG; j++) b = fmaf(ALPHA, b, xv[j]);

    // ---- warp Kogge-Stone affine scan, per-segment coefficient A = alpha^8 ----
    const float A8 = apow(SEG);          // ~0.27249
    float cp = A8;
    float v  = b;
    #pragma unroll
    for (int d = 1; d < 32; d <<= 1) {
        float up = __shfl_up_sync(0xffffffffu, v, d);
        if (lane >= d) v = fmaf(cp, up, v);
        cp *= cp;
    }
    if (lane == 31) wsum[w] = v;   // warp-local end state (entering state 0)
    __syncthreads();

    // cross-warp carry: alpha^(8*32) = alpha^256 ~ 8.5e-19, so the state at a
    // warp boundary is the previous warp's local total to fp32 precision.
    float carry = (w > 0) ? wsum[w - 1] : 0.0f;

    // pass 2 scan with carry injected at lane 0
    float b2 = b + ((lane == 0) ? A8 * carry : 0.0f);
    cp = A8;
    v  = b2;
    #pragma unroll
    for (int d = 1; d < 32; d <<= 1) {
        float up = __shfl_up_sync(0xffffffffu, v, d);
        if (lane >= d) v = fmaf(cp, up, v);
        cp *= cp;
    }
    float excl = __shfl_up_sync(0xffffffffu, v, 1);  // entering state for my segment
    if (lane == 0) excl = carry;

    // ---- final pass: rescan segment with true entering state, write to smem ----
    float yv = excl;
    #pragma unroll
    for (int j = 0; j < SEG; j++) {
        yv = fmaf(ALPHA, yv, xv[j]);
        s[sbase + j] = yv;
    }
    __syncthreads();

    // ---- stage out: padded smem -> coalesced global (skip halo) ----
    const int obase = rowbase + chunk * CHUNK;
    #pragma unroll
    for (int p = 0; p < (CHUNK + THREADS - 1) / THREADS; p++) {
        int i = tid + p * THREADS;
        if (i < CHUNK) {
            int si = i + HALO;
            y[obase + i] = s[si + (si >> 5)];
        }
    }
}

extern "C" void kernel_launch(void* const* d_in, const int* in_sizes, int n_in,
                              void* d_out, int out_size)
{
    const float* x = (const float*)d_in[0];
    float*       y = (float*)d_out;

    const int n    = in_sizes[0];          // 61,440,000
    const int rows = n / ROWLEN;           // 64
    dim3 grid(ROWLEN / CHUNK, rows);       // (120, 64)
    deemph_kernel<<<grid, THREADS>>>(x, y);
}

// round 15
// speedup vs baseline: 1.1777x; 1.1777x over previous
#include <cuda_runtime.h>

// DeEmphasis: y[n] = x[n] + ALPHA*y[n-1], zero init, per row (64 x 960000 fp32).
//
// R14 = R12 (best: 78.8us, 512 thr / SEG=16) with ONE change: occupancy hint
// (512,3) -> (512,4). regs=32 fits 2048 thr/SM exactly; smem 4x34KB=136KB ok.
// R13's failure (1024thr, 2 blocks/SM, 92us) showed the cost of too few
// resident blocks: each block's barrier-separated compute phase silences its
// share of memory concurrency. A 4th resident block fills those gaps.
//
// Structure: block owns 8000-sample payload + 192 halo (alpha^192 ~ 2e-14).
// Phased: coalesced load -> padded smem -> per-thread 16-elem serial scan ->
// warp Kogge-Stone affine scan (coef alpha^16) -> cross-warp carry via smem
// (alpha^512 ~ 7e-37 -> carry = prev warp total) -> rescan with true
// entering state -> smem -> coalesced store.

#define ALPHA 0.85f

static constexpr int ROWLEN  = 960000;
static constexpr int CHUNK   = 8000;   // payload per block
static constexpr int HALO    = 192;    // alpha^192 ~ 2e-14, below fp32 eps
static constexpr int TOTAL   = CHUNK + HALO;      // 8192
static constexpr int THREADS = 512;
static constexpr int SEG     = TOTAL / THREADS;   // 16 elems per thread
static constexpr int SPAD    = TOTAL + TOTAL / 32; // 8448 floats, +1 pad / 32

// compile-time alpha^n
__host__ __device__ constexpr float apow(int n) {
    double r = 1.0;
    for (int i = 0; i < n; i++) r *= (double)ALPHA;
    return (float)r;
}

__global__ void __launch_bounds__(THREADS, 4)
deemph_kernel(const float* __restrict__ x, float* __restrict__ y)
{
    const int chunk = blockIdx.x;          // 0..119
    const int row   = blockIdx.y;          // 0..63
    const int tid   = threadIdx.x;
    const int lane  = tid & 31;
    const int w     = tid >> 5;            // 0..15

    __shared__ float s[SPAD];
    __shared__ float wsum[THREADS / 32];

    const int rowbase = row * ROWLEN;
    const int cstart  = chunk * CHUNK - HALO;   // first (halo) column, may be <0

    // ---- stage in: coalesced global -> padded smem ----
    #pragma unroll
    for (int p = 0; p < TOTAL / THREADS; p++) {
        int i   = tid + p * THREADS;
        int col = cstart + i;
        float v = (col >= 0) ? x[rowbase + col] : 0.0f;   // zero-init history
        s[i + (i >> 5)] = v;
    }
    __syncthreads();

    // ---- per-thread segment into registers (stride 17, odd -> conflict-free) ----
    float xv[SEG];
    const int sbase = tid * SEG + (tid * SEG >> 5);   // = tid*17 for SEG=16
    #pragma unroll
    for (int j = 0; j < SEG; j++) xv[j] = s[sbase + j];

    // pass 1: segment total with zero entering state
    float b = 0.0f;
    #pragma unroll
    for (int j = 0; j < SEG; j++) b = fmaf(ALPHA, b, xv[j]);

    // ---- warp Kogge-Stone affine scan, per-segment coefficient A = alpha^16 ----
    const float A16 = apow(SEG);         // ~0.07425
    float cp = A16;
    float v  = b;
    #pragma unroll
    for (int d = 1; d < 32; d <<= 1) {
        float up = __shfl_up_sync(0xffffffffu, v, d);
        if (lane >= d) v = fmaf(cp, up, v);
        cp *= cp;
    }
    if (lane == 31) wsum[w] = v;   // warp-local end state (entering state 0)
    __syncthreads();

    // cross-warp carry: alpha^(16*32) = alpha^512 ~ 7e-37, so the state at a
    // warp boundary is the previous warp's local total to fp32 precision.
    float carry = (w > 0) ? wsum[w - 1] : 0.0f;

    // pass 2 scan with carry injected at lane 0
    float b2 = b + ((lane == 0) ? A16 * carry : 0.0f);
    cp = A16;
    v  = b2;
    #pragma unroll
    for (int d = 1; d < 32; d <<= 1) {
        float up = __shfl_up_sync(0xffffffffu, v, d);
        if (lane >= d) v = fmaf(cp, up, v);
        cp *= cp;
    }
    float excl = __shfl_up_sync(0xffffffffu, v, 1);  // entering state for my segment
    if (lane == 0) excl = carry;

    // ---- final pass: rescan segment with true entering state, write to smem ----
    float yv = excl;
    #pragma unroll
    for (int j = 0; j < SEG; j++) {
        yv = fmaf(ALPHA, yv, xv[j]);
        s[sbase + j] = yv;
    }
    __syncthreads();

    // ---- stage out: padded smem -> coalesced global (skip halo) ----
    const int obase = rowbase + chunk * CHUNK;
    #pragma unroll
    for (int p = 0; p < (CHUNK + THREADS - 1) / THREADS; p++) {
        int i = tid + p * THREADS;
        if (i < CHUNK) {
            int si = i + HALO;
            y[obase + i] = s[si + (si >> 5)];
        }
    }
}

extern "C" void kernel_launch(void* const* d_in, const int* in_sizes, int n_in,
                              void* d_out, int out_size)
{
    const float* x = (const float*)d_in[0];
    float*       y = (float*)d_out;

    const int n    = in_sizes[0];          // 61,440,000
    const int rows = n / ROWLEN;           // 64
    dim3 grid(ROWLEN / CHUNK, rows);       // (120, 64)
    deemph_kernel<<<grid, THREADS>>>(x, y);
}

// round 16
// speedup vs baseline: 1.2098x; 1.0273x over previous
#include <cuda_runtime.h>

// DeEmphasis: y[n] = x[n] + ALPHA*y[n-1], zero init, per row (64 x 960000 fp32).
//
// R16 = R14 champion (78.3us: 512 thr, SEG=16, launch_bounds(512,4), padded
// smem, phased) with ONE change: float4 GLOBAL staging (LDG.128/STG.128 +
// scalar smem scatter/gather). 4x fewer global instructions + less address
// ALU; smem layout and the whole compute core untouched.
// Alignment: CHUNK=8000, HALO=192 both %16==0 -> float4 bases 64B-aligned.
// Banks: element j of thread t hits bank (4t + t/8 + j)%32, a permutation
// over t for fixed j -> conflict-free.

#define ALPHA 0.85f

static constexpr int ROWLEN  = 960000;
static constexpr int CHUNK   = 8000;   // payload per block
static constexpr int HALO    = 192;    // alpha^192 ~ 2e-14, below fp32 eps
static constexpr int TOTAL   = CHUNK + HALO;      // 8192
static constexpr int THREADS = 512;
static constexpr int SEG     = TOTAL / THREADS;   // 16 elems per thread
static constexpr int SPAD    = TOTAL + TOTAL / 32; // 8448 floats, +1 pad / 32
static constexpr int NV_IN   = TOTAL / 4;         // 2048 float4 (= 4*512)
static constexpr int NV_OUT  = CHUNK / 4;         // 2000 float4

// compile-time alpha^n
__host__ __device__ constexpr float apow(int n) {
    double r = 1.0;
    for (int i = 0; i < n; i++) r *= (double)ALPHA;
    return (float)r;
}

__global__ void __launch_bounds__(THREADS, 4)
deemph_kernel(const float* __restrict__ x, float* __restrict__ y)
{
    const int chunk = blockIdx.x;          // 0..119
    const int row   = blockIdx.y;          // 0..63
    const int tid   = threadIdx.x;
    const int lane  = tid & 31;
    const int w     = tid >> 5;            // 0..15

    __shared__ float s[SPAD];
    __shared__ float wsum[THREADS / 32];

    const int rowbase = row * ROWLEN;
    const int cstart  = chunk * CHUNK - HALO;   // first (halo) column, may be <0

    // ---- stage in: float4 global -> padded smem (scalar scatter) ----
    #pragma unroll
    for (int p = 0; p < NV_IN / THREADS; p++) {
        int idx = tid + p * THREADS;            // float4 index, 0..2047
        int i   = idx * 4;                      // element index in tile
        int col = cstart + i;
        float4 v;
        if (col >= 0) v = *(const float4*)(x + rowbase + col);
        else          v = make_float4(0.f, 0.f, 0.f, 0.f);  // zero history
        s[i     + ((i    ) >> 5)] = v.x;
        s[i + 1 + ((i + 1) >> 5)] = v.y;
        s[i + 2 + ((i + 2) >> 5)] = v.z;
        s[i + 3 + ((i + 3) >> 5)] = v.w;
    }
    __syncthreads();

    // ---- per-thread segment into registers (stride 17, odd -> conflict-free) ----
    float xv[SEG];
    const int sbase = tid * SEG + (tid * SEG >> 5);   // = tid*17 for SEG=16
    #pragma unroll
    for (int j = 0; j < SEG; j++) xv[j] = s[sbase + j];

    // pass 1: segment total with zero entering state
    float b = 0.0f;
    #pragma unroll
    for (int j = 0; j < SEG; j++) b = fmaf(ALPHA, b, xv[j]);

    // ---- warp Kogge-Stone affine scan, per-segment coefficient A = alpha^16 ----
    const float A16 = apow(SEG);         // ~0.07425
    float cp = A16;
    float v  = b;
    #pragma unroll
    for (int d = 1; d < 32; d <<= 1) {
        float up = __shfl_up_sync(0xffffffffu, v, d);
        if (lane >= d) v = fmaf(cp, up, v);
        cp *= cp;
    }
    if (lane == 31) wsum[w] = v;   // warp-local end state (entering state 0)
    __syncthreads();

    // cross-warp carry: alpha^(16*32) = alpha^512 ~ 7e-37, so the state at a
    // warp boundary is the previous warp's local total to fp32 precision.
    float carry = (w > 0) ? wsum[w - 1] : 0.0f;

    // pass 2 scan with carry injected at lane 0
    float b2 = b + ((lane == 0) ? A16 * carry : 0.0f);
    cp = A16;
    v  = b2;
    #pragma unroll
    for (int d = 1; d < 32; d <<= 1) {
        float up = __shfl_up_sync(0xffffffffu, v, d);
        if (lane >= d) v = fmaf(cp, up, v);
        cp *= cp;
    }
    float excl = __shfl_up_sync(0xffffffffu, v, 1);  // entering state for my segment
    if (lane == 0) excl = carry;

    // ---- final pass: rescan segment with true entering state, write to smem ----
    float yv = excl;
    #pragma unroll
    for (int j = 0; j < SEG; j++) {
        yv = fmaf(ALPHA, yv, xv[j]);
        s[sbase + j] = yv;
    }
    __syncthreads();

    // ---- stage out: padded smem (scalar gather) -> float4 global ----
    const int obase = rowbase + chunk * CHUNK;
    #pragma unroll
    for (int p = 0; p < (NV_OUT + THREADS - 1) / THREADS; p++) {
        int idx = tid + p * THREADS;            // float4 index, 0..1999
        if (idx < NV_OUT) {
            int i  = idx * 4;                   // payload element index
            int si = i + HALO;                  // tile element index
            float4 v;
            v.x = s[si     + ((si    ) >> 5)];
            v.y = s[si + 1 + ((si + 1) >> 5)];
            v.z = s[si + 2 + ((si + 2) >> 5)];
            v.w = s[si + 3 + ((si + 3) >> 5)];
            *(float4*)(y + obase + i) = v;
        }
    }
}

extern "C" void kernel_launch(void* const* d_in, const int* in_sizes, int n_in,
                              void* d_out, int out_size)
{
    const float* x = (const float*)d_in[0];
    float*       y = (float*)d_out;

    const int n    = in_sizes[0];          // 61,440,000
    const int rows = n / ROWLEN;           // 64
    dim3 grid(ROWLEN / CHUNK, rows);       // (120, 64)
    deemph_kernel<<<grid, THREADS>>>(x, y);
}

// round 17
// speedup vs baseline: 1.2103x; 1.0004x over previous
#include <cuda_runtime.h>

// DeEmphasis: y[n] = x[n] + ALPHA*y[n-1], zero init, per row (64 x 960000 fp32).
//
// R17 = R16 (76.3us) with the smem side vectorized too: padding moved from
// +1 float per 32 floats to +1 float4 per 8 float4s (16B pad per 128B), so
// EVERY smem access is 128-bit:
//   stage-in : 1 STS.128/float4 (was 4 STS + shift math)
//   compute  : thread t reads/writes s4[4t + t/2 + j], j=0..3 (LDS/STS.128);
//              per-8-lane-phase banks {0,16,4,20,8,24,12,28}+span -> clean
//   stage-out: 1 LDS.128/float4, 8-aligned groups -> clean
// Scan core and element order untouched. Global staging float4 as in R16.

#define ALPHA 0.85f

static constexpr int ROWLEN  = 960000;
static constexpr int CHUNK   = 8000;   // payload per block
static constexpr int HALO    = 192;    // alpha^192 ~ 2e-14, below fp32 eps
static constexpr int TOTAL   = CHUNK + HALO;      // 8192
static constexpr int THREADS = 512;
static constexpr int SEG     = TOTAL / THREADS;   // 16 elems per thread
static constexpr int NV_IN   = TOTAL / 4;         // 2048 float4
static constexpr int NV_OUT  = CHUNK / 4;         // 2000 float4
static constexpr int HALO4   = HALO / 4;          // 48 (multiple of 8)
static constexpr int SPAD4   = NV_IN + NV_IN / 8; // 2304 float4 = 36 KB

// compile-time alpha^n
__host__ __device__ constexpr float apow(int n) {
    double r = 1.0;
    for (int i = 0; i < n; i++) r *= (double)ALPHA;
    return (float)r;
}

__global__ void __launch_bounds__(THREADS, 4)
deemph_kernel(const float* __restrict__ x, float* __restrict__ y)
{
    const int chunk = blockIdx.x;          // 0..119
    const int row   = blockIdx.y;          // 0..63
    const int tid   = threadIdx.x;
    const int lane  = tid & 31;
    const int w     = tid >> 5;            // 0..15

    __shared__ float4 s4[SPAD4];
    __shared__ float  wsum[THREADS / 32];

    const int rowbase = row * ROWLEN;
    const int cstart  = chunk * CHUNK - HALO;   // first (halo) column, may be <0

    // ---- stage in: float4 global -> float4 padded smem ----
    #pragma unroll
    for (int p = 0; p < NV_IN / THREADS; p++) {
        int f   = tid + p * THREADS;            // float4 tile index, 0..2047
        int col = cstart + f * 4;
        float4 v;
        if (col >= 0) v = *(const float4*)(x + rowbase + col);
        else          v = make_float4(0.f, 0.f, 0.f, 0.f);  // zero history
        s4[f + (f >> 3)] = v;
    }
    __syncthreads();

    // ---- per-thread segment: 4x LDS.128 (padded: base 4t + t/2) ----
    const int sb = 4 * tid + (tid >> 1);
    float4 q0 = s4[sb + 0];
    float4 q1 = s4[sb + 1];
    float4 q2 = s4[sb + 2];
    float4 q3 = s4[sb + 3];
    float xv[SEG] = {q0.x,q0.y,q0.z,q0.w, q1.x,q1.y,q1.z,q1.w,
                     q2.x,q2.y,q2.z,q2.w, q3.x,q3.y,q3.z,q3.w};

    // pass 1: segment total with zero entering state
    float b = 0.0f;
    #pragma unroll
    for (int j = 0; j < SEG; j++) b = fmaf(ALPHA, b, xv[j]);

    // ---- warp Kogge-Stone affine scan, per-segment coefficient A = alpha^16 ----
    const float A16 = apow(SEG);         // ~0.07425
    float cp = A16;
    float v  = b;
    #pragma unroll
    for (int d = 1; d < 32; d <<= 1) {
        float up = __shfl_up_sync(0xffffffffu, v, d);
        if (lane >= d) v = fmaf(cp, up, v);
        cp *= cp;
    }
    if (lane == 31) wsum[w] = v;   // warp-local end state (entering state 0)
    __syncthreads();

    // cross-warp carry: alpha^(16*32) = alpha^512 ~ 7e-37 -> state at a warp
    // boundary is the previous warp's local total to fp32 precision.
    float carry = (w > 0) ? wsum[w - 1] : 0.0f;

    // pass 2 scan with carry injected at lane 0
    float b2 = b + ((lane == 0) ? A16 * carry : 0.0f);
    cp = A16;
    v  = b2;
    #pragma unroll
    for (int d = 1; d < 32; d <<= 1) {
        float up = __shfl_up_sync(0xffffffffu, v, d);
        if (lane >= d) v = fmaf(cp, up, v);
        cp *= cp;
    }
    float excl = __shfl_up_sync(0xffffffffu, v, 1);  // entering state for my segment
    if (lane == 0) excl = carry;

    // ---- final pass: rescan with true entering state, 4x STS.128 back ----
    {
        float yv = excl;
        #pragma unroll
        for (int j = 0; j < SEG; j++) { yv = fmaf(ALPHA, yv, xv[j]); xv[j] = yv; }
        s4[sb + 0] = make_float4(xv[0],  xv[1],  xv[2],  xv[3]);
        s4[sb + 1] = make_float4(xv[4],  xv[5],  xv[6],  xv[7]);
        s4[sb + 2] = make_float4(xv[8],  xv[9],  xv[10], xv[11]);
        s4[sb + 3] = make_float4(xv[12], xv[13], xv[14], xv[15]);
    }
    __syncthreads();

    // ---- stage out: float4 padded smem -> float4 global (skip halo) ----
    const int obase = rowbase + chunk * CHUNK;
    #pragma unroll
    for (int p = 0; p < (NV_OUT + THREADS - 1) / THREADS; p++) {
        int idx = tid + p * THREADS;            // payload float4 index
        if (idx < NV_OUT) {
            int f = idx + HALO4;                // tile float4 index
            float4 vv = s4[f + (f >> 3)];
            *(float4*)(y + obase + idx * 4) = vv;
        }
    }
}

extern "C" void kernel_launch(void* const* d_in, const int* in_sizes, int n_in,
                              void* d_out, int out_size)
{
    const float* x = (const float*)d_in[0];
    float*       y = (float*)d_out;

    const int n    = in_sizes[0];          // 61,440,000
    const int rows = n / ROWLEN;           // 64
    dim3 grid(ROWLEN / CHUNK, rows);       // (120, 64)
    deemph_kernel<<<grid, THREADS>>>(x, y);
}